// round 7
// baseline (speedup 1.0000x reference)
#include <cuda_runtime.h>
#include <cuda_bf16.h>
#include <cstdint>

#define C 80
#define KB 32                  // items per tile (halved; 2-ahead prefetch)
#define PITCH 88               // halves per item row (80 + 8 pad), conflict-free ldmatrix
#define NWARPS 5
#define NTHREADS 160
#define GRID 592               // 4 CTAs per SM x 148
#define LPT 4                  // float4 loads per thread per tile (32*80/4/160)

__device__ float g_cooc[C * C];
__device__ unsigned int g_count;

__global__ __launch_bounds__(NTHREADS, 4)
void fused_kernel(const float* __restrict__ label,
                  const float* __restrict__ pre_adj,
                  float* __restrict__ out, int batch) {
    __shared__ __nv_bfloat16 sT[2][KB * PITCH];   // double-buffered [item][class] bf16
    __shared__ float red[NWARPS];
    __shared__ int s_last;

    const int tid  = threadIdx.x;
    const int warp = tid >> 5;     // 0..4 : row-block w
    const int lane = tid & 31;
    const int g    = lane >> 2;
    const int t    = lane & 3;
    const int gi   = lane >> 3;    // ldmatrix group 0..3
    const int li   = lane & 7;

    uint32_t smem_u32;
    { uint64_t tmp; asm("cvta.to.shared.u64 %0, %1;" : "=l"(tmp) : "l"((void*)&sT[0][0]));
      smem_u32 = (uint32_t)tmp; }

    // trans-ldmatrix geometry (proven R2-R6)
    const int a_cls    = warp * 16 + ((gi & 1) ? 8 : 0);
    const int a_kbase  = ((gi & 2) ? 8 : 0) + li;
    const int b_clsadd = (gi & 2) ? 8 : 0;
    const int b_kbase  = ((gi & 1) ? 8 : 0) + li;

    const int bj0 = warp;
    const int bj1 = (warp + 1) % 5;
    const int bj2 = (warp + 2) % 5;

    float d[3][2][4];
    #pragma unroll
    for (int b = 0; b < 3; b++)
        #pragma unroll
        for (int n = 0; n < 2; n++)
            #pragma unroll
            for (int q = 0; q < 4; q++) d[b][n][q] = 0.0f;

    // fill coordinates: 640 float4 over 160 threads -> 4 each
    const int st_item = tid / (C / 4);            // 0..7 (base item; +8 per p)
    const int st_c4   = (tid % (C / 4)) * 4;

    const int numTiles = (batch + KB - 1) / KB;

#define LOADSET(ST, T) do {                                                     \
        const float* p0_ = label + (long long)(T) * KB * C                      \
                         + (long long)st_item * C + st_c4;                      \
        _Pragma("unroll")                                                       \
        for (int p_ = 0; p_ < LPT; p_++)                                        \
            ST[p_] = *(const float4*)(p0_ + (long long)p_ * 8 * C);             \
    } while (0)

#define BODY(ST, BUFIDX, TILE) do {                                             \
        __nv_bfloat16* buf_ = &sT[BUFIDX][0];                                   \
        _Pragma("unroll")                                                       \
        for (int p_ = 0; p_ < LPT; p_++) {                                      \
            uint32_t lo_, hi_;                                                  \
            asm("prmt.b32 %0, %1, %2, 0x7632;" : "=r"(lo_)                      \
                : "r"(__float_as_uint(ST[p_].x)), "r"(__float_as_uint(ST[p_].y))); \
            asm("prmt.b32 %0, %1, %2, 0x7632;" : "=r"(hi_)                      \
                : "r"(__float_as_uint(ST[p_].z)), "r"(__float_as_uint(ST[p_].w))); \
            *(uint2*)&buf_[(st_item + p_ * 8) * PITCH + st_c4] = make_uint2(lo_, hi_); \
        }                                                                       \
        /* refill this set for tile+2*GRID; 2 tile-periods to complete */       \
        { const int t2_ = (TILE) + 2 * GRID;                                    \
          if (t2_ < numTiles) LOADSET(ST, t2_); }                               \
        __syncthreads();                                                        \
        const uint32_t sbase_ = smem_u32 + (uint32_t)((BUFIDX) * KB * PITCH * 2); \
        _Pragma("unroll")                                                       \
        for (int ks_ = 0; ks_ < KB / 16; ks_++) {                               \
            const int k0_ = ks_ * 16;                                           \
            uint32_t a0_, a1_, a2_, a3_;                                        \
            { uint32_t addr_ = sbase_ + (uint32_t)(((k0_ + a_kbase) * PITCH + a_cls) * 2); \
              asm volatile("ldmatrix.sync.aligned.m8n8.x4.trans.shared.b16 "    \
                           "{%0,%1,%2,%3}, [%4];"                               \
                           : "=r"(a0_), "=r"(a1_), "=r"(a2_), "=r"(a3_) : "r"(addr_)); } \
            const int bjs_[3] = {bj0, bj1, bj2};                                \
            _Pragma("unroll")                                                   \
            for (int b_ = 0; b_ < 3; b_++) {                                    \
                const int n0_ = bjs_[b_] * 16;                                  \
                uint32_t b0_, b1_, b2_, b3_;                                    \
                uint32_t addr_ = sbase_ + (uint32_t)(((k0_ + b_kbase) * PITCH + n0_ + b_clsadd) * 2); \
                asm volatile("ldmatrix.sync.aligned.m8n8.x4.trans.shared.b16 "  \
                             "{%0,%1,%2,%3}, [%4];"                             \
                             : "=r"(b0_), "=r"(b1_), "=r"(b2_), "=r"(b3_) : "r"(addr_)); \
                asm volatile(                                                   \
                    "mma.sync.aligned.m16n8k16.row.col.f32.bf16.bf16.f32 "      \
                    "{%0,%1,%2,%3}, {%4,%5,%6,%7}, {%8,%9}, {%0,%1,%2,%3};\n"   \
                    : "+f"(d[b_][0][0]), "+f"(d[b_][0][1]), "+f"(d[b_][0][2]), "+f"(d[b_][0][3]) \
                    : "r"(a0_), "r"(a1_), "r"(a2_), "r"(a3_), "r"(b0_), "r"(b1_)); \
                asm volatile(                                                   \
                    "mma.sync.aligned.m16n8k16.row.col.f32.bf16.bf16.f32 "      \
                    "{%0,%1,%2,%3}, {%4,%5,%6,%7}, {%8,%9}, {%0,%1,%2,%3};\n"   \
                    : "+f"(d[b_][1][0]), "+f"(d[b_][1][1]), "+f"(d[b_][1][2]), "+f"(d[b_][1][3]) \
                    : "r"(a0_), "r"(a1_), "r"(a2_), "r"(a3_), "r"(b2_), "r"(b3_)); \
            }                                                                   \
        }                                                                       \
    } while (0)

    float4 stA[LPT], stB[LPT];
    int tile = blockIdx.x;
    if (tile < numTiles)        LOADSET(stA, tile);
    if (tile + GRID < numTiles) LOADSET(stB, tile + GRID);

    while (tile < numTiles) {
        BODY(stA, 0, tile);
        tile += GRID;
        if (tile >= numTiles) break;
        BODY(stB, 1, tile);
        tile += GRID;
    }

    // ---- flush partials (integer-valued f32 -> exact, order-independent) ----
    {
        const int bjs[3] = {bj0, bj1, bj2};
        #pragma unroll
        for (int b = 0; b < 3; b++) {
            const int row = warp * 16 + g;
            #pragma unroll
            for (int n = 0; n < 2; n++) {
                const int col = bjs[b] * 16 + n * 8 + 2 * t;
                atomicAdd(&g_cooc[(row)     * C + col],     d[b][n][0]);
                atomicAdd(&g_cooc[(row)     * C + col + 1], d[b][n][1]);
                atomicAdd(&g_cooc[(row + 8) * C + col],     d[b][n][2]);
                atomicAdd(&g_cooc[(row + 8) * C + col + 1], d[b][n][3]);
            }
        }
    }

    // ---- last-CTA finalize ----
    __threadfence();
    __syncthreads();
    if (tid == 0)
        s_last = (atomicAdd(&g_count, 1u) == (unsigned)gridDim.x - 1u) ? 1 : 0;
    __syncthreads();
    if (!s_last) return;

    float sum = 0.0f;
    for (int idx = tid; idx < C * C; idx += NTHREADS) {
        int i = idx / C, j = idx - i * C;
        int bi = i >> 4, bj = j >> 4;
        int dd = bj - bi; if (dd < 0) dd += 5;
        float cooc = (dd <= 2) ? g_cooc[i * C + j] : g_cooc[j * C + i];  // symmetry mirror
        float cnt  = g_cooc[i * C + i];
        float adj  = (i == j) ? 1.0f : __fdividef(cooc, cnt + 1e-7f);
        float r = fabsf(pre_adj[idx] - adj);
        sum += (r < 1.0f) ? (r * r) : (r - 0.5f);
    }
    #pragma unroll
    for (int o = 16; o > 0; o >>= 1) sum += __shfl_down_sync(0xffffffffu, sum, o);
    if (lane == 0) red[warp] = sum;
    __syncthreads();
    if (warp == 0) {
        float v = (lane < NWARPS) ? red[lane] : 0.0f;
        #pragma unroll
        for (int o = 16; o > 0; o >>= 1) v += __shfl_down_sync(0xffffffffu, v, o);
        if (lane == 0) out[0] = v / (float)(C * C);
    }
    __syncthreads();   // all g_cooc reads complete before re-zero
    for (int idx = tid; idx < C * C; idx += NTHREADS) g_cooc[idx] = 0.0f;
    if (tid == 0) g_count = 0u;
}

extern "C" void kernel_launch(void* const* d_in, const int* in_sizes, int n_in,
                              void* d_out, int out_size) {
    const float* pre_adj = (const float*)d_in[0];
    const float* label   = (const float*)d_in[1];
    const int batch = in_sizes[1] / C;

    fused_kernel<<<GRID, NTHREADS>>>(label, pre_adj, (float*)d_out, batch);
}